// round 15
// baseline (speedup 1.0000x reference)
#include <cuda_runtime.h>
#include <cuda_bf16.h>

// ---------------------------------------------------------------------------
// Fused LSTMMeasurementPredictor — round 15: tensor-core GEMMs, 2 CTAs/SM
//   B=131072, H=128, NQ=2, P=32, D_IN=17, T=16
// R14 mma.sync bf16 3-term-split GEMMs, BT halved to 16 so SMEM ~111.6 KB
// -> 2 CTAs/SM (occ 50%) to hide the serial phase latency. x and cell-h are
// updated in place (consumers run before producers in the phase order), so
// the ping-pong buffers are gone. __launch_bounds__(512,2) pins regs <= 64.
// ---------------------------------------------------------------------------

#define NTH 512
#define BT  16
#define SS  20    // padded row stride for [K][16] state buffers
#define GS  20    // G row count stride unused; G uses 16-wide rows, stride GSW
#define GSW 16    // G row width (16 batches, no pad)

// smem layout (floats)
constexpr int OFF_X   = 0;                    // 17  rows : x (in-place)
constexpr int OFF_HC  = OFF_X   + 17  * SS;   // 128 rows : cell h (in-place)
constexpr int OFF_S   = OFF_HC  + 128 * SS;   // 128 rows : s staging
constexpr int OFF_CC  = OFF_S   + 128 * SS;   // 128 rows : cell c
constexpr int OFF_C0  = OFF_CC  + 128 * SS;   // 128 rows : lstm0 c
constexpr int OFF_C1  = OFF_C0  + 128 * SS;   // 128 rows : lstm1 c
constexpr int OFF_H0  = OFF_C1  + 128 * SS;   // 32  rows : lstm0 proj h
constexpr int OFF_H1  = OFF_H0  + 32  * SS;   // 32  rows : lstm1 proj h
constexpr int OFF_RHO = OFF_H1  + 32  * SS;   // 16*33    : rho
constexpr int OFF_V   = OFF_RHO + 16 * 33;    // 8 rows   : projector v
constexpr int OFF_G   = OFF_V   + 8 * SS;     // 512 x 16 : gate staging
constexpr int OFF_XCH = OFF_G   + 512 * GSW;  // 1280 u32 : X hi frags (10 ch)
constexpr int OFF_XCL = OFF_XCH + 1280;       // 1280 u32 : X lo frags
constexpr int SMEM_FLOATS = OFF_XCL + 1280;
constexpr int SMEM_BYTES  = SMEM_FLOATS * 4;  // ~111.6 KB -> 2 CTAs/SM

// A-fragment-packed weights (identical layout to R14):
// uint4 index = (chunk*32 + mfrag)*32 + lane ; one zero pad chunk at end.
__device__ __align__(16) unsigned g_WcH[11 * 4096];
__device__ __align__(16) unsigned g_WcL[11 * 4096];
__device__ __align__(16) unsigned g_W0H[5 * 4096];
__device__ __align__(16) unsigned g_W0L[5 * 4096];
__device__ __align__(16) unsigned g_W1H[5 * 4096];
__device__ __align__(16) unsigned g_W1L[5 * 4096];
__device__ __align__(16) float g_bc[512];   // gate-interleaved (j = 4u+g)
__device__ __align__(16) float g_b0[512];
__device__ __align__(16) float g_b1[512];
__device__ __align__(16) float g_Whr0T[128 * 32];
__device__ __align__(16) float g_Whr1T[128 * 32];
__device__ __align__(16) float g_WpT[128 * 8];

__device__ __forceinline__ void split2(float x0, float x1,
                                       unsigned& hp, unsigned& lp) {
    __nv_bfloat16 h0 = __float2bfloat16(x0);
    __nv_bfloat16 h1 = __float2bfloat16(x1);
    float l0f = x0 - __bfloat162float(h0);
    float l1f = x1 - __bfloat162float(h1);
    __nv_bfloat16 l0 = __float2bfloat16(l0f);
    __nv_bfloat16 l1 = __float2bfloat16(l1f);
    hp = ((unsigned)__bfloat16_as_ushort(h1) << 16) | __bfloat16_as_ushort(h0);
    lp = ((unsigned)__bfloat16_as_ushort(l1) << 16) | __bfloat16_as_ushort(l0);
}

__global__ void prep_kernel(
    const float* __restrict__ Wihc, const float* __restrict__ Whhc,
    const float* __restrict__ bihc, const float* __restrict__ bhhc,
    const float* __restrict__ Wp,
    const float* __restrict__ Wih0, const float* __restrict__ Whh0,
    const float* __restrict__ bih0, const float* __restrict__ bhh0,
    const float* __restrict__ Whr0,
    const float* __restrict__ Wih1, const float* __restrict__ Whh1,
    const float* __restrict__ bih1, const float* __restrict__ bhh1,
    const float* __restrict__ Whr1)
{
    int i0 = blockIdx.x * blockDim.x + threadIdx.x;
    int stride = gridDim.x * blockDim.x;

    // cell: logical W[j][k], j=4u+g -> orig row g*128+u; K=145
    for (int i = i0; i < 11 * 4096; i += stride) {
        int r = i & 3, lane = (i >> 2) & 31, mf = (i >> 7) & 31, ch = i >> 12;
        int gr = lane >> 2, q = lane & 3;
        int j = mf * 16 + gr + (r & 1) * 8;
        int k = ch * 16 + 2 * q + (r >> 1) * 8;
        int u = j >> 2, g = j & 3, orow = g * 128 + u;
        float w0 = (k < 17) ? Wihc[orow * 17 + k]
                 : (k < 145 ? Whhc[orow * 128 + (k - 17)] : 0.f);
        int k1 = k + 1;
        float w1 = (k1 < 17) ? Wihc[orow * 17 + k1]
                 : (k1 < 145 ? Whhc[orow * 128 + (k1 - 17)] : 0.f);
        unsigned hp, lp; split2(w0, w1, hp, lp);
        g_WcH[i] = hp; g_WcL[i] = lp;
    }
    // lstm0: [x(17); hp0(32)] K=49
    for (int i = i0; i < 5 * 4096; i += stride) {
        int r = i & 3, lane = (i >> 2) & 31, mf = (i >> 7) & 31, ch = i >> 12;
        int gr = lane >> 2, q = lane & 3;
        int j = mf * 16 + gr + (r & 1) * 8;
        int k = ch * 16 + 2 * q + (r >> 1) * 8;
        int u = j >> 2, g = j & 3, orow = g * 128 + u;
        float w0 = (k < 17) ? Wih0[orow * 17 + k]
                 : (k < 49 ? Whh0[orow * 32 + (k - 17)] : 0.f);
        int k1 = k + 1;
        float w1 = (k1 < 17) ? Wih0[orow * 17 + k1]
                 : (k1 < 49 ? Whh0[orow * 32 + (k1 - 17)] : 0.f);
        unsigned hp, lp; split2(w0, w1, hp, lp);
        g_W0H[i] = hp; g_W0L[i] = lp;
    }
    // lstm1: [hp0(32); hp1(32)] K=64
    for (int i = i0; i < 5 * 4096; i += stride) {
        int r = i & 3, lane = (i >> 2) & 31, mf = (i >> 7) & 31, ch = i >> 12;
        int gr = lane >> 2, q = lane & 3;
        int j = mf * 16 + gr + (r & 1) * 8;
        int k = ch * 16 + 2 * q + (r >> 1) * 8;
        int u = j >> 2, g = j & 3, orow = g * 128 + u;
        float w0 = (k < 32) ? Wih1[orow * 32 + k]
                 : (k < 64 ? Whh1[orow * 32 + (k - 32)] : 0.f);
        int k1 = k + 1;
        float w1 = (k1 < 32) ? Wih1[orow * 32 + k1]
                 : (k1 < 64 ? Whh1[orow * 32 + (k1 - 32)] : 0.f);
        unsigned hp, lp; split2(w0, w1, hp, lp);
        g_W1H[i] = hp; g_W1L[i] = lp;
    }
    for (int i = i0; i < 512; i += stride) {
        int u = i >> 2, g = i & 3, j = g * 128 + u;
        g_bc[i] = bihc[j] + bhhc[j];
        g_b0[i] = bih0[j] + bhh0[j];
        g_b1[i] = bih1[j] + bhh1[j];
    }
    for (int i = i0; i < 128 * 32; i += stride) {
        int k = i >> 5, n = i & 31;
        g_Whr0T[i] = Whr0[n * 128 + k];
        g_Whr1T[i] = Whr1[n * 128 + k];
    }
    for (int i = i0; i < 128 * 8; i += stride) {
        int k = i >> 3, n = i & 7;
        g_WpT[i] = Wp[n * 128 + k];
    }
}

// ---------------------------------------------------------------------------
__device__ __forceinline__ float htanh(float x) {
    float y;
    asm("tanh.approx.f32 %0, %1;" : "=f"(y) : "f"(x));
    return y;
}
__device__ __forceinline__ float fsig(float x) {
    return fmaf(0.5f, htanh(0.5f * x), 0.5f);
}

__device__ __forceinline__ void mma16816(float& d0, float& d1, float& d2,
                                         float& d3, const uint4& a,
                                         unsigned b0, unsigned b1) {
    asm volatile(
        "mma.sync.aligned.m16n8k16.row.col.f32.bf16.bf16.f32 "
        "{%0,%1,%2,%3}, {%4,%5,%6,%7}, {%8,%9}, {%0,%1,%2,%3};"
        : "+f"(d0), "+f"(d1), "+f"(d2), "+f"(d3)
        : "r"(a.x), "r"(a.y), "r"(a.z), "r"(a.w), "r"(b0), "r"(b1));
}

// fp32 -> bf16 hi/lo conversion of X[K,16] into fragment layout:
// XC[(ch*16 + n)*8 + e] = bf16x2(X[ch*16+2e][n], X[ch*16+2e+1][n])
template <int KA, int KB, int CH>
__device__ __forceinline__ void conv_bf16(
    const float* srcA, const float* srcB,
    unsigned* XCH, unsigned* XCL, int tid)
{
    for (int i = tid; i < CH * 128; i += NTH) {
        int e = i & 7, n = (i >> 3) & 15, ch = i >> 7;
        int k = ch * 16 + 2 * e;
        float x0 = (k < KA) ? srcA[k * SS + n]
                 : (k < KA + KB ? srcB[(k - KA) * SS + n] : 0.f);
        int k1 = k + 1;
        float x1 = (k1 < KA) ? srcA[k1 * SS + n]
                 : (k1 < KA + KB ? srcB[(k1 - KA) * SS + n] : 0.f);
        unsigned hp, lp; split2(x0, x1, hp, lp);
        XCH[i] = hp; XCL[i] = lp;
    }
}

// G[512,16] = W @ X via mma.sync, 3-term bf16 split, 16 warps x 2 mfrags.
template <int CH>
__device__ __forceinline__ void mma_gemm(
    const unsigned* __restrict__ WH, const unsigned* __restrict__ WL,
    const unsigned* XCH, const unsigned* XCL, float* G, int tid)
{
    const int w = tid >> 5, lane = tid & 31, gr = lane >> 2, q = lane & 3;
    float d[2][2][4];
#pragma unroll
    for (int m = 0; m < 2; ++m)
#pragma unroll
        for (int nf = 0; nf < 2; ++nf)
#pragma unroll
            for (int r = 0; r < 4; ++r) d[m][nf][r] = 0.f;

    const uint4* pH = (const uint4*)WH;
    const uint4* pL = (const uint4*)WL;
    const int base0 = 2 * w * 32 + lane;
    uint4 aH0 = pH[base0], aH1 = pH[base0 + 32];
    uint4 aL0 = pL[base0], aL1 = pL[base0 + 32];

#pragma unroll
    for (int ch = 0; ch < CH; ++ch) {
        int nb = (ch + 1) * 1024 + base0;       // pad chunk makes this safe
        uint4 nH0 = pH[nb], nH1 = pH[nb + 32];
        uint4 nL0 = pL[nb], nL1 = pL[nb + 32];
#pragma unroll
        for (int nf = 0; nf < 2; ++nf) {
            int xb = (ch * 16 + nf * 8 + gr) * 8;
            unsigned bh0 = XCH[xb + q], bh1 = XCH[xb + q + 4];
            unsigned bl0 = XCL[xb + q], bl1 = XCL[xb + q + 4];
            mma16816(d[0][nf][0], d[0][nf][1], d[0][nf][2], d[0][nf][3], aH0, bh0, bh1);
            mma16816(d[1][nf][0], d[1][nf][1], d[1][nf][2], d[1][nf][3], aH1, bh0, bh1);
            mma16816(d[0][nf][0], d[0][nf][1], d[0][nf][2], d[0][nf][3], aH0, bl0, bl1);
            mma16816(d[1][nf][0], d[1][nf][1], d[1][nf][2], d[1][nf][3], aH1, bl0, bl1);
            mma16816(d[0][nf][0], d[0][nf][1], d[0][nf][2], d[0][nf][3], aL0, bh0, bh1);
            mma16816(d[1][nf][0], d[1][nf][1], d[1][nf][2], d[1][nf][3], aL1, bh0, bh1);
        }
        aH0 = nH0; aH1 = nH1; aL0 = nL0; aL1 = nL1;
    }
#pragma unroll
    for (int m = 0; m < 2; ++m) {
        int R = w * 32 + m * 16;
#pragma unroll
        for (int nf = 0; nf < 2; ++nf) {
            int col = nf * 8 + 2 * q;
            *(float2*)(G + (R + gr) * GSW + col)     = make_float2(d[m][nf][0], d[m][nf][1]);
            *(float2*)(G + (R + gr + 8) * GSW + col) = make_float2(d[m][nf][2], d[m][nf][3]);
        }
    }
}

// gate epilogue: thread = (unit u = tid>>2, batches bb..bb+3, bb=(tid&3)*4)
__device__ __forceinline__ void gate_epilogue(
    const float* __restrict__ bias, const float* G,
    float* C, float* Sout, int tid)
{
    const int u = tid >> 2;
    const int bb = (tid & 3) * 4;
    float4 bs = __ldg((const float4*)(bias + 4 * u));
    const float bsa[4] = {bs.x, bs.y, bs.z, bs.w};
    float gv[4][4];
#pragma unroll
    for (int g = 0; g < 4; ++g) {
        float4 v = *(const float4*)(G + (4 * u + g) * GSW + bb);
        gv[g][0] = v.x + bsa[g]; gv[g][1] = v.y + bsa[g];
        gv[g][2] = v.z + bsa[g]; gv[g][3] = v.w + bsa[g];
    }
    float* cp = C + u * SS + bb;
    float4 c0 = *(const float4*)cp;
    float cb[4] = {c0.x, c0.y, c0.z, c0.w};
    float sb[4];
#pragma unroll
    for (int j = 0; j < 4; ++j) {
        float cn = fsig(gv[1][j]) * cb[j] + fsig(gv[0][j]) * htanh(gv[2][j]);
        cb[j] = cn;
        sb[j] = fsig(gv[3][j]) * htanh(cn);
    }
    *(float4*)cp = make_float4(cb[0], cb[1], cb[2], cb[3]);
    *(float4*)(Sout + u * SS + bb) = make_float4(sb[0], sb[1], sb[2], sb[3]);
}

// hp[32,16]: h'[n][b] = sum_k s[k][b] * WhrT[k*32+n]. 512 threads, 1 out each.
__device__ __forceinline__ void proj_gemm(
    const float* __restrict__ WT, const float* shS, float* dst,
    float* outp, int tid)
{
    const int n = tid & 31;
    const int b = tid >> 5;
    float acc = 0.f;
#pragma unroll 8
    for (int k = 0; k < 128; ++k)
        acc += shS[k * SS + b] * __ldg(&WT[k * 32 + n]);
    dst[n * SS + b] = acc;
    if (outp)
        outp[(size_t)b * 512 + n] = acc;
}

// v[8,16]: v[nn][b] = sum_k h[k][b] WpT[k*8+nn] + bp[nn]. 128 threads.
__device__ __forceinline__ void wp_gemm(
    const float* __restrict__ bp, const float* shH, float* shV, int tid)
{
    if (tid >= 128) return;
    const int nn = tid >> 4;
    const int b  = tid & 15;
    float a = __ldg(&bp[nn]);
#pragma unroll 8
    for (int k = 0; k < 128; ++k)
        a += shH[k * SS + b] * __ldg(&g_WpT[k * 8 + nn]);
    shV[nn * SS + b] = a;
}

// quantum measurement physics for batch element b (0..15); writes x in place
__device__ __forceinline__ void physics(const float* shV, const float* shRHO,
                                        float* shX, int b)
{
    float Mr[2][2][2], Mi[2][2][2];
#pragma unroll
    for (int q = 0; q < 2; ++q) {
        float ar = shV[(q * 4 + 0) * SS + b];
        float ai = shV[(q * 4 + 1) * SS + b];
        float br = shV[(q * 4 + 2) * SS + b];
        float bi = shV[(q * 4 + 3) * SS + b];
        float n00 = ar * ar + ai * ai;
        float n11 = br * br + bi * bi;
        float inv = 1.0f / (n00 + n11);
        float pr = (ar * br + ai * bi) * inv;
        float pi = (ai * br - ar * bi) * inv;
        Mr[q][0][0] = n00 * inv; Mi[q][0][0] = 0.f;
        Mr[q][0][1] = pr;        Mi[q][0][1] = pi;
        Mr[q][1][0] = pr;        Mi[q][1][0] = -pi;
        Mr[q][1][1] = n11 * inv; Mi[q][1][1] = 0.f;
    }
    const float* rp = shRHO + b * 33;
    float m = 0.f;
#pragma unroll
    for (int a = 0; a < 2; ++a)
#pragma unroll
        for (int c = 0; c < 2; ++c)
#pragma unroll
            for (int b2 = 0; b2 < 2; ++b2)
#pragma unroll
                for (int d = 0; d < 2; ++d) {
                    float tr_ = Mr[0][a][c] * Mr[1][b2][d] - Mi[0][a][c] * Mi[1][b2][d];
                    float ti_ = Mr[0][a][c] * Mi[1][b2][d] + Mi[0][a][c] * Mr[1][b2][d];
                    int row = c * 2 + d, col = a * 2 + b2;
                    float rr = rp[row * 4 + col];
                    float ri = rp[16 + row * 4 + col];
                    m += tr_ * rr - ti_ * ri;
                }
    shX[0 * SS + b] = m;
#pragma unroll
    for (int q = 0; q < 2; ++q)
#pragma unroll
        for (int i = 0; i < 2; ++i)
#pragma unroll
            for (int j = 0; j < 2; ++j) {
                int base = 1 + 8 * q + 4 * i + 2 * j;
                shX[base * SS + b]       = Mr[q][i][j];
                shX[(base + 1) * SS + b] = Mi[q][i][j];
            }
}

__global__ void __launch_bounds__(NTH, 2) fused_kernel(
    const float* __restrict__ meas, const float* __restrict__ basis_r,
    const float* __restrict__ basis_i, const float* __restrict__ rho,
    const float* __restrict__ h0in, const float* __restrict__ c0in,
    const float* __restrict__ bp, float* __restrict__ out)
{
    extern __shared__ float sm[];
    float* shX   = sm + OFF_X;
    float* shHC  = sm + OFF_HC;
    float* shS   = sm + OFF_S;
    float* shCC  = sm + OFF_CC;
    float* shC0  = sm + OFF_C0;
    float* shC1  = sm + OFF_C1;
    float* shH0  = sm + OFF_H0;
    float* shH1  = sm + OFF_H1;
    float* shRHO = sm + OFF_RHO;
    float* shV   = sm + OFF_V;
    float* shG   = sm + OFF_G;
    unsigned* XCH = (unsigned*)(sm + OFF_XCH);
    unsigned* XCL = (unsigned*)(sm + OFF_XCL);

    const int tid = threadIdx.x;
    const int b0g = blockIdx.x * BT;

    // ---- init loads ----
    for (int i = tid; i < BT; i += NTH)
        shX[0 * SS + i] = meas[b0g + i];
    for (int i = tid; i < BT * 8; i += NTH) {
        int b = i >> 3, e = i & 7;
        shX[(1 + 2 * e) * SS + b] = basis_r[(size_t)(b0g + b) * 8 + e];
        shX[(2 + 2 * e) * SS + b] = basis_i[(size_t)(b0g + b) * 8 + e];
    }
    for (int i = tid; i < BT * 32; i += NTH) {
        int b = i >> 5, e = i & 31;
        shRHO[b * 33 + e] = rho[(size_t)(b0g + b) * 32 + e];
    }
    for (int i = tid; i < BT * 128; i += NTH) {
        int b = i >> 7, u = i & 127;
        shHC[u * SS + b] = h0in[(size_t)(b0g + b) * 128 + u];
        shCC[u * SS + b] = c0in[(size_t)(b0g + b) * 128 + u];
    }
    // zero C0, C1, H0, H1 (contiguous from OFF_C0: 128+128+32+32 rows)
    for (int i = tid; i < 320 * SS; i += NTH)
        sm[OFF_C0 + i] = 0.f;
    __syncthreads();

    for (int t = 0; t < 16; ++t) {
        // ---- lstm0: X = [x(17); h0(32)], K=49 -> 4 chunks ----
        conv_bf16<17, 32, 4>(shX, shH0, XCH, XCL, tid);
        __syncthreads();
        mma_gemm<4>(g_W0H, g_W0L, XCH, XCL, shG, tid);
        __syncthreads();
        gate_epilogue(g_b0, shG, shC0, shS, tid);
        __syncthreads();
        proj_gemm(g_Whr0T, shS, shH0, nullptr, tid);
        __syncthreads();
        // ---- lstm1: X = [hp0(32); hp1(32)], K=64 -> 4 chunks ----
        conv_bf16<32, 32, 4>(shH0, shH1, XCH, XCL, tid);
        __syncthreads();
        mma_gemm<4>(g_W1H, g_W1L, XCH, XCL, shG, tid);
        __syncthreads();
        gate_epilogue(g_b1, shG, shC1, shS, tid);
        __syncthreads();
        proj_gemm(g_Whr1T, shS, shH1,
                  out + (size_t)b0g * 512 + (size_t)t * 32, tid);
        __syncthreads();

        if (t < 15) {
            // ---- cell: X = [x(17); h(128)], K=145 -> 10 chunks ----
            conv_bf16<17, 128, 10>(shX, shHC, XCH, XCL, tid);
            __syncthreads();
            mma_gemm<10>(g_WcH, g_WcL, XCH, XCL, shG, tid);
            __syncthreads();
            gate_epilogue(g_bc, shG, shCC, shHC, tid);   // h_new in place
            __syncthreads();
            wp_gemm(bp, shHC, shV, tid);
            __syncthreads();
            if (tid < BT) physics(shV, shRHO, shX, tid); // x_{t+1} in place
            __syncthreads();
        }
    }
}

extern "C" void kernel_launch(void* const* d_in, const int* in_sizes, int n_in,
                              void* d_out, int out_size)
{
    const float* meas   = (const float*)d_in[0];
    const float* br     = (const float*)d_in[1];
    const float* bi     = (const float*)d_in[2];
    const float* rho    = (const float*)d_in[3];
    const float* h0     = (const float*)d_in[4];
    const float* c0     = (const float*)d_in[5];
    const float* Wihc   = (const float*)d_in[6];
    const float* Whhc   = (const float*)d_in[7];
    const float* bihc   = (const float*)d_in[8];
    const float* bhhc   = (const float*)d_in[9];
    const float* Wp     = (const float*)d_in[10];
    const float* bp     = (const float*)d_in[11];
    const float* Wih0   = (const float*)d_in[12];
    const float* Whh0   = (const float*)d_in[13];
    const float* bih0   = (const float*)d_in[14];
    const float* bhh0   = (const float*)d_in[15];
    const float* Whr0   = (const float*)d_in[16];
    const float* Wih1   = (const float*)d_in[17];
    const float* Whh1   = (const float*)d_in[18];
    const float* bih1   = (const float*)d_in[19];
    const float* bhh1   = (const float*)d_in[20];
    const float* Whr1   = (const float*)d_in[21];

    int B = in_sizes[0];
    int nblocks = B / BT;

    cudaFuncSetAttribute(fused_kernel,
                         cudaFuncAttributeMaxDynamicSharedMemorySize,
                         SMEM_BYTES);

    prep_kernel<<<256, 256>>>(Wihc, Whhc, bihc, bhhc, Wp,
                              Wih0, Whh0, bih0, bhh0, Whr0,
                              Wih1, Whh1, bih1, bhh1, Whr1);

    fused_kernel<<<nblocks, NTH, SMEM_BYTES>>>(
        meas, br, bi, rho, h0, c0, bp, (float*)d_out);
}

// round 16
// speedup vs baseline: 1.3238x; 1.3238x over previous
#include <cuda_runtime.h>
#include <cuda_bf16.h>

// ---------------------------------------------------------------------------
// Fused LSTMMeasurementPredictor — round 16: fused-epilogue tensor GEMMs
//   B=131072, H=128, NQ=2, P=32, D_IN=17, T=16
// R14 base (BT=32, 512 thr, mma.sync bf16 3-term split). NEW: weight rows
// permuted so the 4 gates of unit u=w*8+gr land in one thread's D frags
// (mfrag 2w rows gr/gr+8 = gates i,f ; mfrag 2w+1 = gates g,o). The LSTM
// epilogue runs in registers straight after the MMA loop: no G staging
// buffer, 3 fewer phases/barriers per step. x and cell-h update in place.
// ---------------------------------------------------------------------------

#define NTH 512
#define BT  32
#define SS  36   // padded row stride for [K][32] state buffers

// smem layout (floats)
constexpr int OFF_X   = 0;                    // 17  rows : x (in place)
constexpr int OFF_HC  = OFF_X   + 17  * SS;   // 128 rows : cell h (in place)
constexpr int OFF_S   = OFF_HC  + 128 * SS;   // 128 rows : s staging
constexpr int OFF_CC  = OFF_S   + 128 * SS;   // 128 rows : cell c
constexpr int OFF_C0  = OFF_CC  + 128 * SS;   // 128 rows : lstm0 c
constexpr int OFF_C1  = OFF_C0  + 128 * SS;   // 128 rows : lstm1 c
constexpr int OFF_H0  = OFF_C1  + 128 * SS;   // 32  rows : lstm0 proj h
constexpr int OFF_H1  = OFF_H0  + 32  * SS;   // 32  rows : lstm1 proj h
constexpr int OFF_RHO = OFF_H1  + 32  * SS;   // 32*33    : rho
constexpr int OFF_V   = OFF_RHO + 32 * 33;    // 8 rows   : projector v
constexpr int OFF_XCH = OFF_V   + 8 * SS;     // 2560 u32 : X hi frags (10 ch)
constexpr int OFF_XCL = OFF_XCH + 2560;       // 2560 u32 : X lo frags
constexpr int SMEM_FLOATS = OFF_XCL + 2560;
constexpr int SMEM_BYTES  = SMEM_FLOATS * 4;  // ~127 KB

// A-fragment-packed weights, GATE-ALIGNED permutation:
// uint4 index = (chunk*32 + mf)*32 + lane ; mf = 2w+m ; lane = (gr,q).
// frag row (gr, half) of mfrag mf  <->  orig row gate*128 + u
//   with u = (mf>>1)*8 + gr , gate = ((mf&1)<<1) | half.
// One zero pad chunk at the end of each array.
__device__ __align__(16) unsigned g_WcH[11 * 4096];
__device__ __align__(16) unsigned g_WcL[11 * 4096];
__device__ __align__(16) unsigned g_W0H[5 * 4096];
__device__ __align__(16) unsigned g_W0L[5 * 4096];
__device__ __align__(16) unsigned g_W1H[5 * 4096];
__device__ __align__(16) unsigned g_W1L[5 * 4096];
__device__ __align__(16) float g_bc[512];   // gate-interleaved (j = 4u+g)
__device__ __align__(16) float g_b0[512];
__device__ __align__(16) float g_b1[512];
__device__ __align__(16) float g_Whr0T[128 * 32];
__device__ __align__(16) float g_Whr1T[128 * 32];
__device__ __align__(16) float g_WpT[128 * 8];

__device__ __forceinline__ void split2(float x0, float x1,
                                       unsigned& hp, unsigned& lp) {
    __nv_bfloat16 h0 = __float2bfloat16(x0);
    __nv_bfloat16 h1 = __float2bfloat16(x1);
    float l0f = x0 - __bfloat162float(h0);
    float l1f = x1 - __bfloat162float(h1);
    __nv_bfloat16 l0 = __float2bfloat16(l0f);
    __nv_bfloat16 l1 = __float2bfloat16(l1f);
    hp = ((unsigned)__bfloat16_as_ushort(h1) << 16) | __bfloat16_as_ushort(h0);
    lp = ((unsigned)__bfloat16_as_ushort(l1) << 16) | __bfloat16_as_ushort(l0);
}

__global__ void prep_kernel(
    const float* __restrict__ Wihc, const float* __restrict__ Whhc,
    const float* __restrict__ bihc, const float* __restrict__ bhhc,
    const float* __restrict__ Wp,
    const float* __restrict__ Wih0, const float* __restrict__ Whh0,
    const float* __restrict__ bih0, const float* __restrict__ bhh0,
    const float* __restrict__ Whr0,
    const float* __restrict__ Wih1, const float* __restrict__ Whh1,
    const float* __restrict__ bih1, const float* __restrict__ bhh1,
    const float* __restrict__ Whr1)
{
    int i0 = blockIdx.x * blockDim.x + threadIdx.x;
    int stride = gridDim.x * blockDim.x;

    // cell: K=145
    for (int i = i0; i < 11 * 4096; i += stride) {
        int r = i & 3, lane = (i >> 2) & 31, mf = (i >> 7) & 31, ch = i >> 12;
        int gr = lane >> 2, q = lane & 3;
        int u = (mf >> 1) * 8 + gr;
        int gate = ((mf & 1) << 1) | (r & 1);
        int orow = gate * 128 + u;
        int k = ch * 16 + 2 * q + (r >> 1) * 8;
        float w0 = (k < 17) ? Wihc[orow * 17 + k]
                 : (k < 145 ? Whhc[orow * 128 + (k - 17)] : 0.f);
        int k1 = k + 1;
        float w1 = (k1 < 17) ? Wihc[orow * 17 + k1]
                 : (k1 < 145 ? Whhc[orow * 128 + (k1 - 17)] : 0.f);
        unsigned hp, lp; split2(w0, w1, hp, lp);
        g_WcH[i] = hp; g_WcL[i] = lp;
    }
    // lstm0: [x(17); hp0(32)] K=49
    for (int i = i0; i < 5 * 4096; i += stride) {
        int r = i & 3, lane = (i >> 2) & 31, mf = (i >> 7) & 31, ch = i >> 12;
        int gr = lane >> 2, q = lane & 3;
        int u = (mf >> 1) * 8 + gr;
        int gate = ((mf & 1) << 1) | (r & 1);
        int orow = gate * 128 + u;
        int k = ch * 16 + 2 * q + (r >> 1) * 8;
        float w0 = (k < 17) ? Wih0[orow * 17 + k]
                 : (k < 49 ? Whh0[orow * 32 + (k - 17)] : 0.f);
        int k1 = k + 1;
        float w1 = (k1 < 17) ? Wih0[orow * 17 + k1]
                 : (k1 < 49 ? Whh0[orow * 32 + (k1 - 17)] : 0.f);
        unsigned hp, lp; split2(w0, w1, hp, lp);
        g_W0H[i] = hp; g_W0L[i] = lp;
    }
    // lstm1: [hp0(32); hp1(32)] K=64
    for (int i = i0; i < 5 * 4096; i += stride) {
        int r = i & 3, lane = (i >> 2) & 31, mf = (i >> 7) & 31, ch = i >> 12;
        int gr = lane >> 2, q = lane & 3;
        int u = (mf >> 1) * 8 + gr;
        int gate = ((mf & 1) << 1) | (r & 1);
        int orow = gate * 128 + u;
        int k = ch * 16 + 2 * q + (r >> 1) * 8;
        float w0 = (k < 32) ? Wih1[orow * 32 + k]
                 : (k < 64 ? Whh1[orow * 32 + (k - 32)] : 0.f);
        int k1 = k + 1;
        float w1 = (k1 < 32) ? Wih1[orow * 32 + k1]
                 : (k1 < 64 ? Whh1[orow * 32 + (k1 - 32)] : 0.f);
        unsigned hp, lp; split2(w0, w1, hp, lp);
        g_W1H[i] = hp; g_W1L[i] = lp;
    }
    // biases in (i,f,g,o)-per-unit order: b[4u+g] = bih[g*128+u] + bhh[...]
    for (int i = i0; i < 512; i += stride) {
        int u = i >> 2, g = i & 3, j = g * 128 + u;
        g_bc[i] = bihc[j] + bhhc[j];
        g_b0[i] = bih0[j] + bhh0[j];
        g_b1[i] = bih1[j] + bhh1[j];
    }
    for (int i = i0; i < 128 * 32; i += stride) {
        int k = i >> 5, n = i & 31;
        g_Whr0T[i] = Whr0[n * 128 + k];
        g_Whr1T[i] = Whr1[n * 128 + k];
    }
    for (int i = i0; i < 128 * 8; i += stride) {
        int k = i >> 3, n = i & 7;
        g_WpT[i] = Wp[n * 128 + k];
    }
}

// ---------------------------------------------------------------------------
typedef unsigned long long ull;

__device__ __forceinline__ void fma2(ull& acc, ull a, ull b) {
    asm("fma.rn.f32x2 %0, %1, %2, %0;" : "+l"(acc) : "l"(a), "l"(b));
}
__device__ __forceinline__ ull dup2(float x) {
    ull r;
    asm("mov.b64 %0, {%1, %1};" : "=l"(r) : "f"(x));
    return r;
}
__device__ __forceinline__ void unpk(ull v, float& lo, float& hi) {
    asm("mov.b64 {%0, %1}, %2;" : "=f"(lo), "=f"(hi) : "l"(v));
}
__device__ __forceinline__ float htanh(float x) {
    float y;
    asm("tanh.approx.f32 %0, %1;" : "=f"(y) : "f"(x));
    return y;
}
__device__ __forceinline__ float fsig(float x) {
    return fmaf(0.5f, htanh(0.5f * x), 0.5f);
}

__device__ __forceinline__ void mma16816(float& d0, float& d1, float& d2,
                                         float& d3, const uint4& a,
                                         unsigned b0, unsigned b1) {
    asm volatile(
        "mma.sync.aligned.m16n8k16.row.col.f32.bf16.bf16.f32 "
        "{%0,%1,%2,%3}, {%4,%5,%6,%7}, {%8,%9}, {%0,%1,%2,%3};"
        : "+f"(d0), "+f"(d1), "+f"(d2), "+f"(d3)
        : "r"(a.x), "r"(a.y), "r"(a.z), "r"(a.w), "r"(b0), "r"(b1));
}

// fp32 -> bf16 hi/lo conversion of X[K,32] into B-fragment layout:
// XC[(ch*32 + n)*8 + e] = bf16x2(X[ch*16+2e][n], X[ch*16+2e+1][n])
template <int KA, int KB, int CH>
__device__ __forceinline__ void conv_bf16(
    const float* srcA, const float* srcB,
    unsigned* XCH, unsigned* XCL, int tid)
{
    for (int i = tid; i < CH * 256; i += NTH) {
        int e = i & 7, n = (i >> 3) & 31, ch = i >> 8;
        int k = ch * 16 + 2 * e;
        float x0 = (k < KA) ? srcA[k * SS + n]
                 : (k < KA + KB ? srcB[(k - KA) * SS + n] : 0.f);
        int k1 = k + 1;
        float x1 = (k1 < KA) ? srcA[k1 * SS + n]
                 : (k1 < KA + KB ? srcB[(k1 - KA) * SS + n] : 0.f);
        unsigned hp, lp; split2(x0, x1, hp, lp);
        XCH[i] = hp; XCL[i] = lp;
    }
}

// LSTM GEMM + fused in-register gate epilogue.
// Thread (w, gr, q) owns unit u = w*8+gr, batches nf*8+2q, nf*8+2q+1 (nf 0..3):
//   d[0][nf][0,1] = gate i ; d[0][nf][2,3] = gate f
//   d[1][nf][0,1] = gate g ; d[1][nf][2,3] = gate o
// Accumulators init'd with biases; epilogue updates C and writes s to Sout.
template <int CH>
__device__ __forceinline__ void mma_lstm(
    const unsigned* __restrict__ WH, const unsigned* __restrict__ WL,
    const unsigned* XCH, const unsigned* XCL,
    const float* __restrict__ bias, float* C, float* Sout, int tid)
{
    const int w = tid >> 5, lane = tid & 31, gr = lane >> 2, q = lane & 3;
    const int u = w * 8 + gr;
    float4 bs = __ldg((const float4*)(bias + 4 * u));   // (bi, bf, bg, bo)

    float d[2][4][4];
#pragma unroll
    for (int nf = 0; nf < 4; ++nf) {
        d[0][nf][0] = bs.x; d[0][nf][1] = bs.x;   // i
        d[0][nf][2] = bs.y; d[0][nf][3] = bs.y;   // f
        d[1][nf][0] = bs.z; d[1][nf][1] = bs.z;   // g
        d[1][nf][2] = bs.w; d[1][nf][3] = bs.w;   // o
    }

    const uint4* pH = (const uint4*)WH;
    const uint4* pL = (const uint4*)WL;
    const int base0 = 2 * w * 32 + lane;
    uint4 aH0 = pH[base0], aH1 = pH[base0 + 32];
    uint4 aL0 = pL[base0], aL1 = pL[base0 + 32];

#pragma unroll
    for (int ch = 0; ch < CH; ++ch) {
        int nb = (ch + 1) * 1024 + base0;       // pad chunk makes this safe
        uint4 nH0 = pH[nb], nH1 = pH[nb + 32];
        uint4 nL0 = pL[nb], nL1 = pL[nb + 32];
#pragma unroll
        for (int nf = 0; nf < 4; ++nf) {
            int xb = (ch * 32 + nf * 8 + gr) * 8;
            unsigned bh0 = XCH[xb + q], bh1 = XCH[xb + q + 4];
            unsigned bl0 = XCL[xb + q], bl1 = XCL[xb + q + 4];
            mma16816(d[0][nf][0], d[0][nf][1], d[0][nf][2], d[0][nf][3], aH0, bh0, bh1);
            mma16816(d[1][nf][0], d[1][nf][1], d[1][nf][2], d[1][nf][3], aH1, bh0, bh1);
            mma16816(d[0][nf][0], d[0][nf][1], d[0][nf][2], d[0][nf][3], aH0, bl0, bl1);
            mma16816(d[1][nf][0], d[1][nf][1], d[1][nf][2], d[1][nf][3], aH1, bl0, bl1);
            mma16816(d[0][nf][0], d[0][nf][1], d[0][nf][2], d[0][nf][3], aL0, bh0, bh1);
            mma16816(d[1][nf][0], d[1][nf][1], d[1][nf][2], d[1][nf][3], aL1, bh0, bh1);
        }
        aH0 = nH0; aH1 = nH1; aL0 = nL0; aL1 = nL1;
    }

    // in-register epilogue: 4 nf x 2 batches
#pragma unroll
    for (int nf = 0; nf < 4; ++nf) {
        int b = nf * 8 + 2 * q;
        float2 cv = *(const float2*)(C + u * SS + b);
        float cn0 = fsig(d[0][nf][2]) * cv.x + fsig(d[0][nf][0]) * htanh(d[1][nf][0]);
        float cn1 = fsig(d[0][nf][3]) * cv.y + fsig(d[0][nf][1]) * htanh(d[1][nf][1]);
        float s0 = fsig(d[1][nf][2]) * htanh(cn0);
        float s1 = fsig(d[1][nf][3]) * htanh(cn1);
        *(float2*)(C + u * SS + b)    = make_float2(cn0, cn1);
        *(float2*)(Sout + u * SS + b) = make_float2(s0, s1);
    }
}

// hp[32,32] = s[128 rows] @ WhrT[128,32]: c2 = tid&15 (cols 2c2,2c2+1),
// b = tid>>4 (0..31). FFMA2 on global compact weights.
__device__ __forceinline__ void proj_gemm(
    const float* __restrict__ WT, const float* shS, float* dst,
    float* outp, int tid)
{
    const int c2 = tid & 15;
    const int b  = tid >> 4;
    ull acc = 0ull;
#pragma unroll 8
    for (int k = 0; k < 128; ++k) {
        ull w = __ldg((const ull*)(WT + k * 32 + 2 * c2));
        ull a = dup2(shS[k * SS + b]);
        fma2(acc, w, a);
    }
    float v0, v1;
    unpk(acc, v0, v1);
    dst[(2 * c2) * SS + b]     = v0;
    dst[(2 * c2 + 1) * SS + b] = v1;
    if (outp)
        *(float2*)(outp + (size_t)b * 512 + 2 * c2) = make_float2(v0, v1);
}

// v[8,32]: v[nn][b] = sum_k h[k][b] WpT[k*8+nn] + bp[nn]. 256 threads.
__device__ __forceinline__ void wp_gemm(
    const float* __restrict__ bp, const float* shH, float* shV, int tid)
{
    if (tid >= 256) return;
    const int nn = tid >> 5;
    const int b  = tid & 31;
    float a = __ldg(&bp[nn]);
#pragma unroll 8
    for (int k = 0; k < 128; ++k)
        a += shH[k * SS + b] * __ldg(&g_WpT[k * 8 + nn]);
    shV[nn * SS + b] = a;
}

// quantum measurement physics for batch element b (0..31); writes x in place
__device__ __forceinline__ void physics(const float* shV, const float* shRHO,
                                        float* shX, int b)
{
    float Mr[2][2][2], Mi[2][2][2];
#pragma unroll
    for (int q = 0; q < 2; ++q) {
        float ar = shV[(q * 4 + 0) * SS + b];
        float ai = shV[(q * 4 + 1) * SS + b];
        float br = shV[(q * 4 + 2) * SS + b];
        float bi = shV[(q * 4 + 3) * SS + b];
        float n00 = ar * ar + ai * ai;
        float n11 = br * br + bi * bi;
        float inv = 1.0f / (n00 + n11);
        float pr = (ar * br + ai * bi) * inv;
        float pi = (ai * br - ar * bi) * inv;
        Mr[q][0][0] = n00 * inv; Mi[q][0][0] = 0.f;
        Mr[q][0][1] = pr;        Mi[q][0][1] = pi;
        Mr[q][1][0] = pr;        Mi[q][1][0] = -pi;
        Mr[q][1][1] = n11 * inv; Mi[q][1][1] = 0.f;
    }
    const float* rp = shRHO + b * 33;
    float m = 0.f;
#pragma unroll
    for (int a = 0; a < 2; ++a)
#pragma unroll
        for (int c = 0; c < 2; ++c)
#pragma unroll
            for (int b2 = 0; b2 < 2; ++b2)
#pragma unroll
                for (int d = 0; d < 2; ++d) {
                    float tr_ = Mr[0][a][c] * Mr[1][b2][d] - Mi[0][a][c] * Mi[1][b2][d];
                    float ti_ = Mr[0][a][c] * Mi[1][b2][d] + Mi[0][a][c] * Mr[1][b2][d];
                    int row = c * 2 + d, col = a * 2 + b2;
                    float rr = rp[row * 4 + col];
                    float ri = rp[16 + row * 4 + col];
                    m += tr_ * rr - ti_ * ri;
                }
    shX[0 * SS + b] = m;
#pragma unroll
    for (int q = 0; q < 2; ++q)
#pragma unroll
        for (int i = 0; i < 2; ++i)
#pragma unroll
            for (int j = 0; j < 2; ++j) {
                int base = 1 + 8 * q + 4 * i + 2 * j;
                shX[base * SS + b]       = Mr[q][i][j];
                shX[(base + 1) * SS + b] = Mi[q][i][j];
            }
}

__global__ void __launch_bounds__(NTH, 1) fused_kernel(
    const float* __restrict__ meas, const float* __restrict__ basis_r,
    const float* __restrict__ basis_i, const float* __restrict__ rho,
    const float* __restrict__ h0in, const float* __restrict__ c0in,
    const float* __restrict__ bp, float* __restrict__ out)
{
    extern __shared__ float sm[];
    float* shX   = sm + OFF_X;
    float* shHC  = sm + OFF_HC;
    float* shS   = sm + OFF_S;
    float* shCC  = sm + OFF_CC;
    float* shC0  = sm + OFF_C0;
    float* shC1  = sm + OFF_C1;
    float* shH0  = sm + OFF_H0;
    float* shH1  = sm + OFF_H1;
    float* shRHO = sm + OFF_RHO;
    float* shV   = sm + OFF_V;
    unsigned* XCH = (unsigned*)(sm + OFF_XCH);
    unsigned* XCL = (unsigned*)(sm + OFF_XCL);

    const int tid = threadIdx.x;
    const int b0g = blockIdx.x * BT;

    // ---- init loads ----
    for (int i = tid; i < BT; i += NTH)
        shX[0 * SS + i] = meas[b0g + i];
    for (int i = tid; i < BT * 8; i += NTH) {
        int b = i >> 3, e = i & 7;
        shX[(1 + 2 * e) * SS + b] = basis_r[(size_t)(b0g + b) * 8 + e];
        shX[(2 + 2 * e) * SS + b] = basis_i[(size_t)(b0g + b) * 8 + e];
    }
    for (int i = tid; i < BT * 32; i += NTH) {
        int b = i >> 5, e = i & 31;
        shRHO[b * 33 + e] = rho[(size_t)(b0g + b) * 32 + e];
    }
    for (int i = tid; i < BT * 128; i += NTH) {
        int b = i >> 7, u = i & 127;
        shHC[u * SS + b] = h0in[(size_t)(b0g + b) * 128 + u];
        shCC[u * SS + b] = c0in[(size_t)(b0g + b) * 128 + u];
    }
    // zero C0, C1, H0, H1 (contiguous from OFF_C0: 128+128+32+32 rows)
    for (int i = tid; i < 320 * SS; i += NTH)
        sm[OFF_C0 + i] = 0.f;
    __syncthreads();

    for (int t = 0; t < 16; ++t) {
        // ---- lstm0: X = [x(17); h0(32)], K=49 -> 4 chunks ----
        conv_bf16<17, 32, 4>(shX, shH0, XCH, XCL, tid);
        __syncthreads();
        mma_lstm<4>(g_W0H, g_W0L, XCH, XCL, g_b0, shC0, shS, tid);
        __syncthreads();
        proj_gemm(g_Whr0T, shS, shH0, nullptr, tid);
        __syncthreads();
        // ---- lstm1: X = [hp0(32); hp1(32)], K=64 -> 4 chunks ----
        conv_bf16<32, 32, 4>(shH0, shH1, XCH, XCL, tid);
        __syncthreads();
        mma_lstm<4>(g_W1H, g_W1L, XCH, XCL, g_b1, shC1, shS, tid);
        __syncthreads();
        proj_gemm(g_Whr1T, shS, shH1,
                  out + (size_t)b0g * 512 + (size_t)t * 32, tid);
        __syncthreads();

        if (t < 15) {
            // ---- cell: X = [x(17); h(128)], K=145 -> 10 chunks ----
            conv_bf16<17, 128, 10>(shX, shHC, XCH, XCL, tid);
            __syncthreads();
            mma_lstm<10>(g_WcH, g_WcL, XCH, XCL, g_bc, shCC, shHC, tid);
            __syncthreads();
            wp_gemm(bp, shHC, shV, tid);
            __syncthreads();
            if (tid < BT) physics(shV, shRHO, shX, tid);
            __syncthreads();
        }
    }
}

extern "C" void kernel_launch(void* const* d_in, const int* in_sizes, int n_in,
                              void* d_out, int out_size)
{
    const float* meas   = (const float*)d_in[0];
    const float* br     = (const float*)d_in[1];
    const float* bi     = (const float*)d_in[2];
    const float* rho    = (const float*)d_in[3];
    const float* h0     = (const float*)d_in[4];
    const float* c0     = (const float*)d_in[5];
    const float* Wihc   = (const float*)d_in[6];
    const float* Whhc   = (const float*)d_in[7];
    const float* bihc   = (const float*)d_in[8];
    const float* bhhc   = (const float*)d_in[9];
    const float* Wp     = (const float*)d_in[10];
    const float* bp     = (const float*)d_in[11];
    const float* Wih0   = (const float*)d_in[12];
    const float* Whh0   = (const float*)d_in[13];
    const float* bih0   = (const float*)d_in[14];
    const float* bhh0   = (const float*)d_in[15];
    const float* Whr0   = (const float*)d_in[16];
    const float* Wih1   = (const float*)d_in[17];
    const float* Whh1   = (const float*)d_in[18];
    const float* bih1   = (const float*)d_in[19];
    const float* bhh1   = (const float*)d_in[20];
    const float* Whr1   = (const float*)d_in[21];

    int B = in_sizes[0];
    int nblocks = B / BT;

    cudaFuncSetAttribute(fused_kernel,
                         cudaFuncAttributeMaxDynamicSharedMemorySize,
                         SMEM_BYTES);

    prep_kernel<<<256, 256>>>(Wihc, Whhc, bihc, bhhc, Wp,
                              Wih0, Whh0, bih0, bhh0, Whr0,
                              Wih1, Whh1, bih1, bhh1, Whr1);

    fused_kernel<<<nblocks, NTH, SMEM_BYTES>>>(
        meas, br, bi, rho, h0, c0, bp, (float*)d_out);
}

// round 17
// speedup vs baseline: 1.5792x; 1.1929x over previous
#include <cuda_runtime.h>
#include <cuda_bf16.h>

// ---------------------------------------------------------------------------
// Fused LSTMMeasurementPredictor — round 17: warp-specialized tensor chains
//   B=131072, H=128, NQ=2, P=32, D_IN=17, T=16
// R16 fused-epilogue mma.sync design + R8 dual-chain warp specialization:
//   group A (warps 0-7):  conv_c -> mma_c(+epi) -> wp -> physics -> x_{t+1}
//   group B (warps 8-15): conv0 -> mma0(+epi) -> proj0 -> conv1 -> mma1 -> proj1
// Group-local bar.sync; ONE CTA barrier per step. X ping-pong; separate
// fragment buffers per group. Weight layout identical to R16 (prep unchanged).
// ---------------------------------------------------------------------------

#define NTH 512
#define BT  32
#define SS  36   // padded row stride for [K][32] state buffers

// smem layout (floats)
constexpr int OFF_XA  = 0;                    // 17  rows : x ping
constexpr int OFF_XB  = OFF_XA  + 17  * SS;   // 17  rows : x pong
constexpr int OFF_HC  = OFF_XB  + 17  * SS;   // 128 rows : cell h (in place)
constexpr int OFF_S   = OFF_HC  + 128 * SS;   // 128 rows : s staging (group B)
constexpr int OFF_CC  = OFF_S   + 128 * SS;   // 128 rows : cell c
constexpr int OFF_C0  = OFF_CC  + 128 * SS;   // 128 rows : lstm0 c
constexpr int OFF_C1  = OFF_C0  + 128 * SS;   // 128 rows : lstm1 c
constexpr int OFF_H0  = OFF_C1  + 128 * SS;   // 32  rows : lstm0 proj h
constexpr int OFF_H1  = OFF_H0  + 32  * SS;   // 32  rows : lstm1 proj h
constexpr int OFF_RHO = OFF_H1  + 32  * SS;   // 32*33    : rho
constexpr int OFF_V   = OFF_RHO + 32 * 33;    // 8 rows   : projector v
constexpr int OFF_AH  = OFF_V   + 8 * SS;     // 2560 u32 : group A X hi frags
constexpr int OFF_AL  = OFF_AH  + 2560;       // 2560 u32 : group A X lo frags
constexpr int OFF_BH  = OFF_AL  + 2560;       // 1024 u32 : group B X hi frags
constexpr int OFF_BL  = OFF_BH  + 1024;       // 1024 u32 : group B X lo frags
constexpr int SMEM_FLOATS = OFF_BL + 1024;
constexpr int SMEM_BYTES  = SMEM_FLOATS * 4;  // ~140 KB

// A-fragment-packed weights, GATE-ALIGNED permutation (same as R16):
// uint4 index = (chunk*32 + mf)*32 + lane ; frag row (gr, half) of mfrag mf
// <-> orig row gate*128 + u with u = (mf>>1)*8 + gr, gate = ((mf&1)<<1)|half.
// One zero pad chunk at the end of each array.
__device__ __align__(16) unsigned g_WcH[11 * 4096];
__device__ __align__(16) unsigned g_WcL[11 * 4096];
__device__ __align__(16) unsigned g_W0H[5 * 4096];
__device__ __align__(16) unsigned g_W0L[5 * 4096];
__device__ __align__(16) unsigned g_W1H[5 * 4096];
__device__ __align__(16) unsigned g_W1L[5 * 4096];
__device__ __align__(16) float g_bc[512];   // (i,f,g,o) per unit: b[4u+g]
__device__ __align__(16) float g_b0[512];
__device__ __align__(16) float g_b1[512];
__device__ __align__(16) float g_Whr0T[128 * 32];
__device__ __align__(16) float g_Whr1T[128 * 32];
__device__ __align__(16) float g_WpT[128 * 8];

__device__ __forceinline__ void split2(float x0, float x1,
                                       unsigned& hp, unsigned& lp) {
    __nv_bfloat16 h0 = __float2bfloat16(x0);
    __nv_bfloat16 h1 = __float2bfloat16(x1);
    float l0f = x0 - __bfloat162float(h0);
    float l1f = x1 - __bfloat162float(h1);
    __nv_bfloat16 l0 = __float2bfloat16(l0f);
    __nv_bfloat16 l1 = __float2bfloat16(l1f);
    hp = ((unsigned)__bfloat16_as_ushort(h1) << 16) | __bfloat16_as_ushort(h0);
    lp = ((unsigned)__bfloat16_as_ushort(l1) << 16) | __bfloat16_as_ushort(l0);
}

__global__ void prep_kernel(
    const float* __restrict__ Wihc, const float* __restrict__ Whhc,
    const float* __restrict__ bihc, const float* __restrict__ bhhc,
    const float* __restrict__ Wp,
    const float* __restrict__ Wih0, const float* __restrict__ Whh0,
    const float* __restrict__ bih0, const float* __restrict__ bhh0,
    const float* __restrict__ Whr0,
    const float* __restrict__ Wih1, const float* __restrict__ Whh1,
    const float* __restrict__ bih1, const float* __restrict__ bhh1,
    const float* __restrict__ Whr1)
{
    int i0 = blockIdx.x * blockDim.x + threadIdx.x;
    int stride = gridDim.x * blockDim.x;

    for (int i = i0; i < 11 * 4096; i += stride) {
        int r = i & 3, lane = (i >> 2) & 31, mf = (i >> 7) & 31, ch = i >> 12;
        int gr = lane >> 2, q = lane & 3;
        int u = (mf >> 1) * 8 + gr;
        int gate = ((mf & 1) << 1) | (r & 1);
        int orow = gate * 128 + u;
        int k = ch * 16 + 2 * q + (r >> 1) * 8;
        float w0 = (k < 17) ? Wihc[orow * 17 + k]
                 : (k < 145 ? Whhc[orow * 128 + (k - 17)] : 0.f);
        int k1 = k + 1;
        float w1 = (k1 < 17) ? Wihc[orow * 17 + k1]
                 : (k1 < 145 ? Whhc[orow * 128 + (k1 - 17)] : 0.f);
        unsigned hp, lp; split2(w0, w1, hp, lp);
        g_WcH[i] = hp; g_WcL[i] = lp;
    }
    for (int i = i0; i < 5 * 4096; i += stride) {
        int r = i & 3, lane = (i >> 2) & 31, mf = (i >> 7) & 31, ch = i >> 12;
        int gr = lane >> 2, q = lane & 3;
        int u = (mf >> 1) * 8 + gr;
        int gate = ((mf & 1) << 1) | (r & 1);
        int orow = gate * 128 + u;
        int k = ch * 16 + 2 * q + (r >> 1) * 8;
        float w0 = (k < 17) ? Wih0[orow * 17 + k]
                 : (k < 49 ? Whh0[orow * 32 + (k - 17)] : 0.f);
        int k1 = k + 1;
        float w1 = (k1 < 17) ? Wih0[orow * 17 + k1]
                 : (k1 < 49 ? Whh0[orow * 32 + (k1 - 17)] : 0.f);
        unsigned hp, lp; split2(w0, w1, hp, lp);
        g_W0H[i] = hp; g_W0L[i] = lp;
    }
    for (int i = i0; i < 5 * 4096; i += stride) {
        int r = i & 3, lane = (i >> 2) & 31, mf = (i >> 7) & 31, ch = i >> 12;
        int gr = lane >> 2, q = lane & 3;
        int u = (mf >> 1) * 8 + gr;
        int gate = ((mf & 1) << 1) | (r & 1);
        int orow = gate * 128 + u;
        int k = ch * 16 + 2 * q + (r >> 1) * 8;
        float w0 = (k < 32) ? Wih1[orow * 32 + k]
                 : (k < 64 ? Whh1[orow * 32 + (k - 32)] : 0.f);
        int k1 = k + 1;
        float w1 = (k1 < 32) ? Wih1[orow * 32 + k1]
                 : (k1 < 64 ? Whh1[orow * 32 + (k1 - 32)] : 0.f);
        unsigned hp, lp; split2(w0, w1, hp, lp);
        g_W1H[i] = hp; g_W1L[i] = lp;
    }
    for (int i = i0; i < 512; i += stride) {
        int u = i >> 2, g = i & 3, j = g * 128 + u;
        g_bc[i] = bihc[j] + bhhc[j];
        g_b0[i] = bih0[j] + bhh0[j];
        g_b1[i] = bih1[j] + bhh1[j];
    }
    for (int i = i0; i < 128 * 32; i += stride) {
        int k = i >> 5, n = i & 31;
        g_Whr0T[i] = Whr0[n * 128 + k];
        g_Whr1T[i] = Whr1[n * 128 + k];
    }
    for (int i = i0; i < 128 * 8; i += stride) {
        int k = i >> 3, n = i & 7;
        g_WpT[i] = Wp[n * 128 + k];
    }
}

// ---------------------------------------------------------------------------
typedef unsigned long long ull;

__device__ __forceinline__ void fma2(ull& acc, ull a, ull b) {
    asm("fma.rn.f32x2 %0, %1, %2, %0;" : "+l"(acc) : "l"(a), "l"(b));
}
__device__ __forceinline__ ull dup2(float x) {
    ull r;
    asm("mov.b64 %0, {%1, %1};" : "=l"(r) : "f"(x));
    return r;
}
__device__ __forceinline__ void unpk(ull v, float& lo, float& hi) {
    asm("mov.b64 {%0, %1}, %2;" : "=f"(lo), "=f"(hi) : "l"(v));
}
__device__ __forceinline__ float htanh(float x) {
    float y;
    asm("tanh.approx.f32 %0, %1;" : "=f"(y) : "f"(x));
    return y;
}
__device__ __forceinline__ float fsig(float x) {
    return fmaf(0.5f, htanh(0.5f * x), 0.5f);
}
#define BARA() asm volatile("bar.sync 1, 256;" ::: "memory")
#define BARB() asm volatile("bar.sync 2, 256;" ::: "memory")

__device__ __forceinline__ void mma16816(float& d0, float& d1, float& d2,
                                         float& d3, const uint4& a,
                                         unsigned b0, unsigned b1) {
    asm volatile(
        "mma.sync.aligned.m16n8k16.row.col.f32.bf16.bf16.f32 "
        "{%0,%1,%2,%3}, {%4,%5,%6,%7}, {%8,%9}, {%0,%1,%2,%3};"
        : "+f"(d0), "+f"(d1), "+f"(d2), "+f"(d3)
        : "r"(a.x), "r"(a.y), "r"(a.z), "r"(a.w), "r"(b0), "r"(b1));
}

// fp32 -> bf16 hi/lo conversion of X[K,32] into B-fragment layout.
// 256-thread group collective.
template <int KA, int KB, int CH>
__device__ __forceinline__ void conv_bf16(
    const float* srcA, const float* srcB,
    unsigned* XCH, unsigned* XCL, int gtid)
{
    for (int i = gtid; i < CH * 256; i += 256) {
        int e = i & 7, n = (i >> 3) & 31, ch = i >> 8;
        int k = ch * 16 + 2 * e;
        float x0 = (k < KA) ? srcA[k * SS + n]
                 : (k < KA + KB ? srcB[(k - KA) * SS + n] : 0.f);
        int k1 = k + 1;
        float x1 = (k1 < KA) ? srcA[k1 * SS + n]
                 : (k1 < KA + KB ? srcB[(k1 - KA) * SS + n] : 0.f);
        unsigned hp, lp; split2(x0, x1, hp, lp);
        XCH[i] = hp; XCL[i] = lp;
    }
}

// LSTM GEMM + fused in-register epilogue, 256-thread (8-warp) group.
// Warp w runs TWO passes p=0,1 with mfrag base 4w+2p; in pass p the thread
// owns unit u = (2w+p)*8 + gr, batches nf*8+2q, nf*8+2q+1 (nf 0..3).
template <int CH>
__device__ __forceinline__ void mma_lstm_ws(
    const unsigned* __restrict__ WH, const unsigned* __restrict__ WL,
    const unsigned* XCH, const unsigned* XCL,
    const float* __restrict__ bias, float* C, float* Sout, int gtid)
{
    const int w = gtid >> 5, lane = gtid & 31, gr = lane >> 2, q = lane & 3;
    const uint4* pH = (const uint4*)WH;
    const uint4* pL = (const uint4*)WL;

#pragma unroll
    for (int p = 0; p < 2; ++p) {
        const int u = (2 * w + p) * 8 + gr;
        float4 bs = __ldg((const float4*)(bias + 4 * u));   // (bi,bf,bg,bo)
        float d[2][4][4];
#pragma unroll
        for (int nf = 0; nf < 4; ++nf) {
            d[0][nf][0] = bs.x; d[0][nf][1] = bs.x;   // i
            d[0][nf][2] = bs.y; d[0][nf][3] = bs.y;   // f
            d[1][nf][0] = bs.z; d[1][nf][1] = bs.z;   // g
            d[1][nf][2] = bs.w; d[1][nf][3] = bs.w;   // o
        }
        const int base0 = (4 * w + 2 * p) * 32 + lane;
        uint4 aH0 = pH[base0], aH1 = pH[base0 + 32];
        uint4 aL0 = pL[base0], aL1 = pL[base0 + 32];
#pragma unroll
        for (int ch = 0; ch < CH; ++ch) {
            int nb = (ch + 1) * 1024 + base0;     // pad chunk makes this safe
            uint4 nH0 = pH[nb], nH1 = pH[nb + 32];
            uint4 nL0 = pL[nb], nL1 = pL[nb + 32];
#pragma unroll
            for (int nf = 0; nf < 4; ++nf) {
                int xb = (ch * 32 + nf * 8 + gr) * 8;
                unsigned bh0 = XCH[xb + q], bh1 = XCH[xb + q + 4];
                unsigned bl0 = XCL[xb + q], bl1 = XCL[xb + q + 4];
                mma16816(d[0][nf][0], d[0][nf][1], d[0][nf][2], d[0][nf][3], aH0, bh0, bh1);
                mma16816(d[1][nf][0], d[1][nf][1], d[1][nf][2], d[1][nf][3], aH1, bh0, bh1);
                mma16816(d[0][nf][0], d[0][nf][1], d[0][nf][2], d[0][nf][3], aH0, bl0, bl1);
                mma16816(d[1][nf][0], d[1][nf][1], d[1][nf][2], d[1][nf][3], aH1, bl0, bl1);
                mma16816(d[0][nf][0], d[0][nf][1], d[0][nf][2], d[0][nf][3], aL0, bh0, bh1);
                mma16816(d[1][nf][0], d[1][nf][1], d[1][nf][2], d[1][nf][3], aL1, bh0, bh1);
            }
            aH0 = nH0; aH1 = nH1; aL0 = nL0; aL1 = nL1;
        }
        // in-register epilogue
#pragma unroll
        for (int nf = 0; nf < 4; ++nf) {
            int b = nf * 8 + 2 * q;
            float2 cv = *(const float2*)(C + u * SS + b);
            float cn0 = fsig(d[0][nf][2]) * cv.x + fsig(d[0][nf][0]) * htanh(d[1][nf][0]);
            float cn1 = fsig(d[0][nf][3]) * cv.y + fsig(d[0][nf][1]) * htanh(d[1][nf][1]);
            float s0 = fsig(d[1][nf][2]) * htanh(cn0);
            float s1 = fsig(d[1][nf][3]) * htanh(cn1);
            *(float2*)(C + u * SS + b)    = make_float2(cn0, cn1);
            *(float2*)(Sout + u * SS + b) = make_float2(s0, s1);
        }
    }
}

// hp[32,32] = s[128,32] proj. 256 threads: c2 = gtid&15 (cols 2c2,2c2+1),
// b0 = gtid>>4 (0..15) -> batches b0 and b0+16. FFMA2 on global weights.
__device__ __forceinline__ void proj_gemm_ws(
    const float* __restrict__ WT, const float* shS, float* dst,
    float* outp, int gtid)
{
    const int c2 = gtid & 15;
    const int b0 = gtid >> 4;
    ull acc0 = 0ull, acc1 = 0ull;
#pragma unroll 8
    for (int k = 0; k < 128; ++k) {
        ull w = __ldg((const ull*)(WT + k * 32 + 2 * c2));
        ull a0 = dup2(shS[k * SS + b0]);
        ull a1 = dup2(shS[k * SS + b0 + 16]);
        fma2(acc0, w, a0);
        fma2(acc1, w, a1);
    }
    float v00, v01, v10, v11;   // v[batch][col]
    unpk(acc0, v00, v01);
    unpk(acc1, v10, v11);
    dst[(2 * c2) * SS + b0]          = v00;
    dst[(2 * c2 + 1) * SS + b0]      = v01;
    dst[(2 * c2) * SS + b0 + 16]     = v10;
    dst[(2 * c2 + 1) * SS + b0 + 16] = v11;
    if (outp) {
        *(float2*)(outp + (size_t)b0 * 512 + 2 * c2)        = make_float2(v00, v01);
        *(float2*)(outp + (size_t)(b0 + 16) * 512 + 2 * c2) = make_float2(v10, v11);
    }
}

// v[8,32]: 256 threads, one output each.
__device__ __forceinline__ void wp_gemm(
    const float* __restrict__ bp, const float* shH, float* shV, int gtid)
{
    const int nn = gtid >> 5;
    const int b  = gtid & 31;
    float a = __ldg(&bp[nn]);
#pragma unroll 8
    for (int k = 0; k < 128; ++k)
        a += shH[k * SS + b] * __ldg(&g_WpT[k * 8 + nn]);
    shV[nn * SS + b] = a;
}

// quantum measurement physics for batch element b (0..31); writes xnxt
__device__ __forceinline__ void physics(const float* shV, const float* shRHO,
                                        float* shX, int b)
{
    float Mr[2][2][2], Mi[2][2][2];
#pragma unroll
    for (int q = 0; q < 2; ++q) {
        float ar = shV[(q * 4 + 0) * SS + b];
        float ai = shV[(q * 4 + 1) * SS + b];
        float br = shV[(q * 4 + 2) * SS + b];
        float bi = shV[(q * 4 + 3) * SS + b];
        float n00 = ar * ar + ai * ai;
        float n11 = br * br + bi * bi;
        float inv = 1.0f / (n00 + n11);
        float pr = (ar * br + ai * bi) * inv;
        float pi = (ai * br - ar * bi) * inv;
        Mr[q][0][0] = n00 * inv; Mi[q][0][0] = 0.f;
        Mr[q][0][1] = pr;        Mi[q][0][1] = pi;
        Mr[q][1][0] = pr;        Mi[q][1][0] = -pi;
        Mr[q][1][1] = n11 * inv; Mi[q][1][1] = 0.f;
    }
    const float* rp = shRHO + b * 33;
    float m = 0.f;
#pragma unroll
    for (int a = 0; a < 2; ++a)
#pragma unroll
        for (int c = 0; c < 2; ++c)
#pragma unroll
            for (int b2 = 0; b2 < 2; ++b2)
#pragma unroll
                for (int d = 0; d < 2; ++d) {
                    float tr_ = Mr[0][a][c] * Mr[1][b2][d] - Mi[0][a][c] * Mi[1][b2][d];
                    float ti_ = Mr[0][a][c] * Mi[1][b2][d] + Mi[0][a][c] * Mr[1][b2][d];
                    int row = c * 2 + d, col = a * 2 + b2;
                    float rr = rp[row * 4 + col];
                    float ri = rp[16 + row * 4 + col];
                    m += tr_ * rr - ti_ * ri;
                }
    shX[0 * SS + b] = m;
#pragma unroll
    for (int q = 0; q < 2; ++q)
#pragma unroll
        for (int i = 0; i < 2; ++i)
#pragma unroll
            for (int j = 0; j < 2; ++j) {
                int base = 1 + 8 * q + 4 * i + 2 * j;
                shX[base * SS + b]       = Mr[q][i][j];
                shX[(base + 1) * SS + b] = Mi[q][i][j];
            }
}

__global__ void __launch_bounds__(NTH, 1) fused_kernel(
    const float* __restrict__ meas, const float* __restrict__ basis_r,
    const float* __restrict__ basis_i, const float* __restrict__ rho,
    const float* __restrict__ h0in, const float* __restrict__ c0in,
    const float* __restrict__ bp, float* __restrict__ out)
{
    extern __shared__ float sm[];
    float* shHC  = sm + OFF_HC;
    float* shS   = sm + OFF_S;
    float* shCC  = sm + OFF_CC;
    float* shC0  = sm + OFF_C0;
    float* shC1  = sm + OFF_C1;
    float* shH0  = sm + OFF_H0;
    float* shH1  = sm + OFF_H1;
    float* shRHO = sm + OFF_RHO;
    float* shV   = sm + OFF_V;
    unsigned* AH = (unsigned*)(sm + OFF_AH);
    unsigned* AL = (unsigned*)(sm + OFF_AL);
    unsigned* BH = (unsigned*)(sm + OFF_BH);
    unsigned* BL = (unsigned*)(sm + OFF_BL);

    const int tid = threadIdx.x;
    const int b0g = blockIdx.x * BT;

    // ---- init loads into XA ----
    for (int i = tid; i < BT; i += NTH)
        sm[OFF_XA + 0 * SS + i] = meas[b0g + i];
    for (int i = tid; i < BT * 8; i += NTH) {
        int b = i >> 3, e = i & 7;
        sm[OFF_XA + (1 + 2 * e) * SS + b] = basis_r[(size_t)(b0g + b) * 8 + e];
        sm[OFF_XA + (2 + 2 * e) * SS + b] = basis_i[(size_t)(b0g + b) * 8 + e];
    }
    for (int i = tid; i < BT * 32; i += NTH) {
        int b = i >> 5, e = i & 31;
        shRHO[b * 33 + e] = rho[(size_t)(b0g + b) * 32 + e];
    }
    for (int i = tid; i < BT * 128; i += NTH) {
        int b = i >> 7, u = i & 127;
        shHC[u * SS + b] = h0in[(size_t)(b0g + b) * 128 + u];
        shCC[u * SS + b] = c0in[(size_t)(b0g + b) * 128 + u];
    }
    // zero C0, C1, H0, H1 (contiguous from OFF_C0: 128+128+32+32 rows)
    for (int i = tid; i < 320 * SS; i += NTH)
        sm[OFF_C0 + i] = 0.f;
    __syncthreads();

    const bool isA = (tid < 256);
    const int gtid = tid & 255;

    float* xcur = sm + OFF_XA;
    float* xnxt = sm + OFF_XB;

    for (int t = 0; t < 16; ++t) {
        if (isA) {
            // group A: cell chain -> x_{t+1} into xnxt, h_new in place
            if (t < 15) {
                conv_bf16<17, 128, 10>(xcur, shHC, AH, AL, gtid);
                BARA();
                mma_lstm_ws<10>(g_WcH, g_WcL, AH, AL, g_bc, shCC, shHC, gtid);
                BARA();
                wp_gemm(bp, shHC, shV, gtid);
                BARA();
                if (gtid < BT) physics(shV, shRHO, xnxt, gtid);
            }
        } else {
            // group B: output chain for step t (reads xcur only)
            conv_bf16<17, 32, 4>(xcur, shH0, BH, BL, gtid);
            BARB();
            mma_lstm_ws<4>(g_W0H, g_W0L, BH, BL, g_b0, shC0, shS, gtid);
            BARB();
            proj_gemm_ws(g_Whr0T, shS, shH0, nullptr, gtid);
            BARB();
            conv_bf16<32, 32, 4>(shH0, shH1, BH, BL, gtid);
            BARB();
            mma_lstm_ws<4>(g_W1H, g_W1L, BH, BL, g_b1, shC1, shS, gtid);
            BARB();
            proj_gemm_ws(g_Whr1T, shS, shH1,
                         out + (size_t)b0g * 512 + (size_t)t * 32, gtid);
        }
        __syncthreads();
        if (t < 15) {
            float* tx = xcur; xcur = xnxt; xnxt = tx;
        }
    }
}

extern "C" void kernel_launch(void* const* d_in, const int* in_sizes, int n_in,
                              void* d_out, int out_size)
{
    const float* meas   = (const float*)d_in[0];
    const float* br     = (const float*)d_in[1];
    const float* bi     = (const float*)d_in[2];
    const float* rho    = (const float*)d_in[3];
    const float* h0     = (const float*)d_in[4];
    const float* c0     = (const float*)d_in[5];
    const float* Wihc   = (const float*)d_in[6];
    const float* Whhc   = (const float*)d_in[7];
    const float* bihc   = (const float*)d_in[8];
    const float* bhhc   = (const float*)d_in[9];
    const float* Wp     = (const float*)d_in[10];
    const float* bp     = (const float*)d_in[11];
    const float* Wih0   = (const float*)d_in[12];
    const float* Whh0   = (const float*)d_in[13];
    const float* bih0   = (const float*)d_in[14];
    const float* bhh0   = (const float*)d_in[15];
    const float* Whr0   = (const float*)d_in[16];
    const float* Wih1   = (const float*)d_in[17];
    const float* Whh1   = (const float*)d_in[18];
    const float* bih1   = (const float*)d_in[19];
    const float* bhh1   = (const float*)d_in[20];
    const float* Whr1   = (const float*)d_in[21];

    int B = in_sizes[0];
    int nblocks = B / BT;

    cudaFuncSetAttribute(fused_kernel,
                         cudaFuncAttributeMaxDynamicSharedMemorySize,
                         SMEM_BYTES);

    prep_kernel<<<256, 256>>>(Wihc, Whhc, bihc, bhhc, Wp,
                              Wih0, Whh0, bih0, bhh0, Whr0,
                              Wih1, Whh1, bih1, bhh1, Whr1);

    fused_kernel<<<nblocks, NTH, SMEM_BYTES>>>(
        meas, br, bi, rho, h0, c0, bp, (float*)d_out);
}